// round 13
// baseline (speedup 1.0000x reference)
#include <cuda_runtime.h>
#include <cstdint>
#include <cstddef>

// ---------------------------------------------------------------------------
// SNN with cochlea front-end.  B=64, T=500, IN=256, HID=512, OUT=35.
//
// R13: fully layer-decoupled pipeline.  The LIF recurrence is per-neuron
// independent given its input currents, so the network unrolls layer by
// layer into parallel kernels (no barrier-coupled serial CTA at all):
//   prep_quant -> cochlea_rs -> cur1_k (R12 verbatim, bit-exact)
//   rec1: 64x512 independent per-neuron recurrences -> spk1 + s1 masks
//   cor2: per-(b,t) early-exit; rare rows get the exact ascending-k
//         correction row (identical fadd order) into g_cur2 + flag
//   rec2 -> cor3 -> rec3 -> cor4 -> rec4 likewise.
// All arithmetic bit-identical to R12 => same rel_err.
// ---------------------------------------------------------------------------

namespace {
constexpr int T_STEPS = 500;
constexpr int BATCH   = 64;
constexpr int N_IN    = 256;
constexpr int N_HID   = 512;
constexpr int N_OUT   = 35;
constexpr int BT      = BATCH * T_STEPS;
constexpr int CH2     = 50;                      // t-chunk per cur1_k CTA
constexpr float SCALEF = (float)((1.0 - 0.001) / 31.0);
constexpr size_t SPK_HID = (size_t)T_STEPS * BATCH * N_HID;
constexpr size_t SPK_OUT = (size_t)T_STEPS * BATCH * N_OUT;
constexpr int WSTR = 132;                        // padded row stride (u32)
constexpr unsigned ZOFF = 256u * WSTR;           // sentinel zero-row offset
constexpr int SW_BYTES = 257 * WSTR * 4;         // 135,696 B dynamic smem
}  // namespace

// Static device scratch (no runtime allocation).
__device__ unsigned char g_w1q[N_IN * N_HID];
__device__ float g_q2T[N_HID * N_HID];
__device__ float g_q3T[N_HID * N_HID];
__device__ float g_q4T[N_HID * N_OUT];
__device__ float g_rs2[N_HID];
__device__ float g_rs3[N_HID];
__device__ float g_rs4[N_OUT];
__device__ unsigned g_chmask[BT * 8];            // cochlea spike masks
__device__ float g_cur1[(size_t)BT * N_HID];     // 65.5 MB layer-1 currents
__device__ float g_cur2[(size_t)BT * N_HID];     // rare-row corrections L2
__device__ float g_cur3[(size_t)BT * N_HID];     // rare-row corrections L3
__device__ float g_cur4[(size_t)BT * N_OUT];     // rare-row corrections L4
__device__ unsigned g_m1[(size_t)BT * 16];       // s1 masks
__device__ unsigned g_m2[(size_t)BT * 16];       // s2 masks
__device__ unsigned g_m3[(size_t)BT * 16];       // s3 masks
__device__ int g_f1[BT], g_f2[BT], g_f3[BT];     // 0 = all-ones (rowsum path)

// Exact replication of reference fake_quant (fp32, round-half-even, no FMA).
__device__ __forceinline__ float quantw(float w) {
    float wc = fminf(fmaxf(w, 0.001f), 1.0f);
    float l  = rintf((wc - 0.001f) / SCALEF);
    return __fadd_rn(__fmul_rn(l, SCALEF), 0.001f);
}

// ---------------------------------------------------------------------------
__global__ void prep_quant(const float* __restrict__ W1, const float* __restrict__ W2,
                           const float* __restrict__ W3, const float* __restrict__ W4) {
    int idx = blockIdx.x * blockDim.x + threadIdx.x;
    if (idx < N_HID * N_IN) {
        int n = idx / N_IN, k = idx % N_IN;
        float wc = fminf(fmaxf(W1[idx], 0.001f), 1.0f);
        float l  = rintf((wc - 0.001f) / SCALEF);
        g_w1q[k * N_HID + n] = (unsigned char)(int)l;
    }
    if (idx < N_HID * N_HID) {
        int n = idx / N_HID, k = idx % N_HID;
        g_q2T[k * N_HID + n] = quantw(W2[idx]);
        g_q3T[k * N_HID + n] = quantw(W3[idx]);
    }
    if (idx < N_OUT * N_HID) {
        int o = idx / N_HID, k = idx % N_HID;
        g_q4T[k * N_OUT + o] = quantw(W4[idx]);
    }
}

// Cochlea (all blocks) + rowsums (blocks 0-1).
__global__ void __launch_bounds__(256, 1) cochlea_rs(
    const float* __restrict__ x, const float* __restrict__ Wch,
    const float* __restrict__ cb)
{
    __shared__ float xs[T_STEPS];
    const int b = blockIdx.x, k = threadIdx.x;
    const int lane = k & 31, warp = k >> 5;
    for (int i = k; i < T_STEPS; i += 256) xs[i] = x[(size_t)b * T_STEPS + i];
    const float wch = Wch[k];
    const float bch = fminf(fmaxf(cb[k], 0.f), 1.f);
    float chm = 0.f;
    __syncthreads();
    for (int t = 0; t < T_STEPS; ++t) {
        float cur = __fmul_rn(xs[t], wch);
        float rst = (chm > 1.f) ? 1.f : 0.f;
        chm = __fadd_rn(__fadd_rn(__fmul_rn(bch, chm), cur), -rst);
        unsigned bal = __ballot_sync(0xffffffffu, chm > 1.f);
        if (lane == 0) g_chmask[((size_t)b * T_STEPS + t) * 8 + warp] = bal;
    }
    if (b < 2) {
        const int n = b * 256 + k;
        float s2 = 0.f, s3 = 0.f;
        for (int kk = 0; kk < N_HID; ++kk) {
            s2 = __fadd_rn(s2, g_q2T[kk * N_HID + n]);
            s3 = __fadd_rn(s3, g_q3T[kk * N_HID + n]);
        }
        g_rs2[n] = s2;
        g_rs3[n] = s3;
        if (n < N_OUT) {
            float s4 = 0.f;
            for (int kk = 0; kk < N_HID; ++kk)
                s4 = __fadd_rn(s4, g_q4T[kk * N_OUT + n]);
            g_rs4[n] = s4;
        }
    }
}

// ---------------------------------------------------------------------------
// cur1_k: R12 verbatim (bit-exact layer-1 currents, time-parallel).
// ---------------------------------------------------------------------------
__global__ void __launch_bounds__(512, 1) cur1_k() {
    const int b    = blockIdx.x;
    const int t0   = blockIdx.y * CH2;
    const int tid  = threadIdx.x;
    const int lane = tid & 31;
    const int warp = tid >> 5;
    const unsigned ltm = (1u << lane) - 1u;

    extern __shared__ unsigned sw32[];
    __shared__ unsigned s_cm[CH2 * 8];
    __shared__ int      s_ccv[CH2];
    __shared__ __align__(16) unsigned s_list[2][264];

    for (int r = warp; r < 256; r += 16) {
        uint4 v = ((const uint4*)(g_w1q + r * N_HID))[lane];
        ((uint4*)(sw32 + r * WSTR))[lane] = v;
    }
    for (int r = tid; r < 256; r += 512) {
        unsigned* p = sw32 + r * WSTR + 128;
        p[0] = 0u; p[1] = 0u; p[2] = 0u; p[3] = 0u;
    }
    if (tid < WSTR) sw32[256 * WSTR + tid] = 0u;

    for (int i = tid; i < (CH2 * 8) / 4; i += 512)
        ((uint4*)s_cm)[i] =
            ((const uint4*)(g_chmask + ((size_t)b * T_STEPS + t0) * 8))[i];
    __syncthreads();
    if (tid < CH2) {
        uint4 a = ((const uint4*)s_cm)[2 * tid];
        uint4 c = ((const uint4*)s_cm)[2 * tid + 1];
        s_ccv[tid] = ((__popc(a.x) + __popc(a.y)) + (__popc(a.z) + __popc(a.w))) +
                     ((__popc(c.x) + __popc(c.y)) + (__popc(c.z) + __popc(c.w)));
    }
    __syncthreads();

    const int sl = lane & 3;
    const int wq = warp * 8 + (lane >> 2);
    float* outp = g_cur1 + ((size_t)b * T_STEPS + t0) * N_HID + tid;

    for (int tt = 0; tt < CH2; ++tt) {
        const int buf = tt & 1;
        const uint4 mA = ((const uint4*)s_cm)[2 * tt];
        const uint4 mB = ((const uint4*)s_cm)[2 * tt + 1];
        const int cc  = s_ccv[tt];
        const int ccq = ((cc + 31) >> 5) << 3;

        if (tid < N_IN) {
            const unsigned bal =
                (warp == 0) ? mA.x : (warp == 1) ? mA.y :
                (warp == 2) ? mA.z : (warp == 3) ? mA.w :
                (warp == 4) ? mB.x : (warp == 5) ? mB.y :
                (warp == 6) ? mB.z : mB.w;
            if ((bal >> lane) & 1u) {
                int off = __popc(bal & ltm);
                if (warp > 0) off += __popc(mA.x);
                if (warp > 1) off += __popc(mA.y);
                if (warp > 2) off += __popc(mA.z);
                if (warp > 3) off += __popc(mA.w);
                if (warp > 4) off += __popc(mB.x);
                if (warp > 5) off += __popc(mB.y);
                if (warp > 6) off += __popc(mB.z);
                s_list[buf][off] = (unsigned)tid * WSTR;
            }
        }
        if (tid < 4 * ccq - cc) s_list[buf][cc + tid] = ZOFF;
        __syncthreads();

        unsigned a02 = 0u, a13 = 0u;
        const int j0 = sl * ccq;
        #pragma unroll 1
        for (int j = j0; j < j0 + ccq; j += 8) {
            const uint4 i0 = *(const uint4*)&s_list[buf][j];
            const uint4 i1 = *(const uint4*)&s_list[buf][j + 4];
            const unsigned va = (sw32[i0.x + wq] + sw32[i0.y + wq]) +
                                (sw32[i0.z + wq] + sw32[i0.w + wq]);
            const unsigned vb = (sw32[i1.x + wq] + sw32[i1.y + wq]) +
                                (sw32[i1.z + wq] + sw32[i1.w + wq]);
            a02 += (va & 0x00FF00FFu) + (vb & 0x00FF00FFu);
            a13 += ((va >> 8) & 0x00FF00FFu) + ((vb >> 8) & 0x00FF00FFu);
        }
        a02 += __shfl_xor_sync(0xffffffffu, a02, 1);
        a13 += __shfl_xor_sync(0xffffffffu, a13, 1);
        a02 += __shfl_xor_sync(0xffffffffu, a02, 2);
        a13 += __shfl_xor_sync(0xffffffffu, a13, 2);
        const unsigned selv = (lane & 1) ? a13 : a02;
        const int lvl = (lane & 2) ? (int)(selv >> 16) : (int)(selv & 0xFFFFu);
        outp[(size_t)tt * N_HID] =
            __fadd_rn(__fmul_rn(0.001f, (float)cc), __fmul_rn(SCALEF, (float)lvl));
    }
}

// ---------------------------------------------------------------------------
// rec1: per-(b,n) layer-1 recurrence.  Grid 256 x 128 threads.
// ---------------------------------------------------------------------------
__global__ void __launch_bounds__(128, 4) rec1_k(
    const float* __restrict__ pb1, float* __restrict__ out)
{
    const int idx  = blockIdx.x * 128 + threadIdx.x;   // 0 .. 32767
    const int b    = idx >> 9;
    const int n    = idx & 511;
    const int lane = threadIdx.x & 31;

    const float beta = fminf(fmaxf(pb1[0], 0.f), 1.f);
    const float* cb = g_cur1 + (size_t)b * T_STEPS * N_HID + n;
    float* osp = out + (size_t)b * N_HID + n;
    unsigned* mko = g_m1 + (size_t)b * T_STEPS * 16 + (n >> 5);

    float m = 0.f;
    float pf[4];
    #pragma unroll
    for (int i = 0; i < 4; ++i) pf[i] = __ldg(cb + (size_t)i * N_HID);

    for (int t = 0; t < T_STEPS; ++t) {
        const float cur = pf[t & 3];
        if (t + 4 < T_STEPS) pf[t & 3] = __ldg(cb + (size_t)(t + 4) * N_HID);
        float r = (m > 1.f) ? 1.f : 0.f;
        m = __fadd_rn(__fadd_rn(__fmul_rn(beta, m), cur), -r);
        const bool s = (m > 1.f);
        osp[(size_t)t * (BATCH * N_HID)] = s ? 1.f : 0.f;
        const unsigned bal = __ballot_sync(0xffffffffu, s);
        if (lane == 0) mko[(size_t)t * 16] = bal;
    }
}

// ---------------------------------------------------------------------------
// rec_mid: per-(b,n) recurrence for layers 2/3 (flag-gated rowsum fast path).
// ---------------------------------------------------------------------------
__global__ void __launch_bounds__(128, 4) rec_mid_k(
    const int* __restrict__ fl, const float* __restrict__ curbuf,
    const float* __restrict__ rsv, const float* __restrict__ pbeta,
    float* __restrict__ outspk, unsigned* __restrict__ mkout)
{
    const int idx  = blockIdx.x * 128 + threadIdx.x;
    const int b    = idx >> 9;
    const int n    = idx & 511;
    const int lane = threadIdx.x & 31;

    const float beta = fminf(fmaxf(pbeta[0], 0.f), 1.f);
    const float rs = rsv[n];
    const int* fb = fl + b * T_STEPS;
    const float* cb = curbuf + (size_t)b * T_STEPS * N_HID + n;
    float* osp = outspk + (size_t)b * N_HID + n;
    unsigned* mko = mkout + (size_t)b * T_STEPS * 16 + (n >> 5);

    float m = 0.f;
    int   ff[4];
    float pf[4];
    #pragma unroll
    for (int i = 0; i < 4; ++i) {
        ff[i] = __ldg(fb + i);
        pf[i] = ff[i] ? __ldg(cb + (size_t)i * N_HID) : 0.f;
    }

    for (int t = 0; t < T_STEPS; ++t) {
        const float cur = ff[t & 3] ? pf[t & 3] : rs;
        if (t + 4 < T_STEPS) {
            const int f = __ldg(fb + t + 4);
            ff[t & 3] = f;
            pf[t & 3] = f ? __ldg(cb + (size_t)(t + 4) * N_HID) : 0.f;
        }
        float r = (m > 1.f) ? 1.f : 0.f;
        m = __fadd_rn(__fadd_rn(__fmul_rn(beta, m), cur), -r);
        const bool s = (m > 1.f);
        osp[(size_t)t * (BATCH * N_HID)] = s ? 1.f : 0.f;
        const unsigned bal = __ballot_sync(0xffffffffu, s);
        if (lane == 0) mko[(size_t)t * 16] = bal;
    }
}

// ---------------------------------------------------------------------------
// cor_hid: per-(b,t) correction rows for layers 2/3.  Grid (64,125) x 512,
// 4 timesteps per CTA; early exit when the source layer spiked everywhere.
// ---------------------------------------------------------------------------
__global__ void __launch_bounds__(512, 2) cor_hid_k(
    const unsigned* __restrict__ mk, const float* __restrict__ qT,
    const float* __restrict__ rsv, float* __restrict__ curb,
    int* __restrict__ fl)
{
    const int b   = blockIdx.x;
    const int tid = threadIdx.x;
    const float rs = rsv[tid];

    for (int jj = 0; jj < 4; ++jj) {
        const int t = blockIdx.y * 4 + jj;
        const size_t row = (size_t)b * T_STEPS + t;
        unsigned mw[16];
        bool allon = true;
        #pragma unroll
        for (int i = 0; i < 16; ++i) {
            mw[i] = __ldg(mk + row * 16 + i);
            allon &= (mw[i] == 0xffffffffu);
        }
        if (allon) {
            if (tid == 0) fl[row] = 0;
            continue;
        }
        float acc = rs;
        int tot = 0;
        #pragma unroll 1
        for (int w = 0; w < 16; ++w) {
            unsigned z = ~mw[w];
            tot += __popc(z);
            while (z) {
                int bb = __ffs(z) - 1; z &= z - 1;
                acc = __fadd_rn(acc, -__ldg(qT + (size_t)(w * 32 + bb) * N_HID + tid));
            }
        }
        curb[row * N_HID + tid] = (tot == N_HID) ? 0.f : acc;
        if (tid == 0) fl[row] = 1;
    }
}

// cor_out: same for layer 4 (35 columns).  Block 64 threads.
__global__ void __launch_bounds__(64, 8) cor_out_k() {
    const int b   = blockIdx.x;
    const int tid = threadIdx.x;
    const float rs = (tid < N_OUT) ? g_rs4[tid] : 0.f;

    for (int jj = 0; jj < 4; ++jj) {
        const int t = blockIdx.y * 4 + jj;
        const size_t row = (size_t)b * T_STEPS + t;
        unsigned mw[16];
        bool allon = true;
        #pragma unroll
        for (int i = 0; i < 16; ++i) {
            mw[i] = __ldg(g_m3 + row * 16 + i);
            allon &= (mw[i] == 0xffffffffu);
        }
        if (allon) {
            if (tid == 0) g_f3[row] = 0;
            continue;
        }
        float acc = rs;
        int tot = 0;
        #pragma unroll 1
        for (int w = 0; w < 16; ++w) {
            unsigned z = ~mw[w];
            tot += __popc(z);
            if (tid < N_OUT) {
                while (z) {
                    int bb = __ffs(z) - 1; z &= z - 1;
                    acc = __fadd_rn(acc, -__ldg(g_q4T + (size_t)(w * 32 + bb) * N_OUT + tid));
                }
            }
        }
        if (tid < N_OUT) g_cur4[row * N_OUT + tid] = (tot == N_HID) ? 0.f : acc;
        if (tid == 0) g_f3[row] = 1;
    }
}

// ---------------------------------------------------------------------------
// rec_out: per-(b,o) layer-4 recurrence; writes spk4 and mem4.
// ---------------------------------------------------------------------------
__global__ void __launch_bounds__(128, 4) rec_out_k(
    const float* __restrict__ pb4, float* __restrict__ out)
{
    const int idx = blockIdx.x * 128 + threadIdx.x;
    if (idx >= BATCH * N_OUT) return;
    const int b = idx / N_OUT;
    const int o = idx % N_OUT;

    const float beta = fminf(fmaxf(pb4[0], 0.f), 1.f);
    const float rs = g_rs4[o];
    const int* fb = g_f3 + b * T_STEPS;
    const float* cb = g_cur4 + (size_t)b * T_STEPS * N_OUT + o;
    float* o4 = out + 3 * SPK_HID + (size_t)b * N_OUT + o;
    float* om = o4 + SPK_OUT;

    float m = 0.f;
    for (int t = 0; t < T_STEPS; ++t) {
        const int f = __ldg(fb + t);
        const float cur = f ? __ldg(cb + (size_t)t * N_OUT) : rs;
        float r = (m > 1.f) ? 1.f : 0.f;
        m = __fadd_rn(__fadd_rn(__fmul_rn(beta, m), cur), -r);
        o4[(size_t)t * (BATCH * N_OUT)] = (m > 1.f) ? 1.f : 0.f;
        om[(size_t)t * (BATCH * N_OUT)] = m;
    }
}

// ---------------------------------------------------------------------------
// Launcher.  Inputs: x, Wch, W1, W2, W3, W4, cochlea_betas, beta1..beta4.
// Output: concat(spk1, spk2, spk3, spk4, mem4), each [T, B, F], float32.
// ---------------------------------------------------------------------------
extern "C" void kernel_launch(void* const* d_in, const int* in_sizes, int n_in,
                              void* d_out, int out_size) {
    const float* x   = (const float*)d_in[0];
    const float* Wch = (const float*)d_in[1];
    const float* W1  = (const float*)d_in[2];
    const float* W2  = (const float*)d_in[3];
    const float* W3  = (const float*)d_in[4];
    const float* W4  = (const float*)d_in[5];
    const float* cb  = (const float*)d_in[6];
    const float* b1  = (const float*)d_in[7];
    const float* b2  = (const float*)d_in[8];
    const float* b3  = (const float*)d_in[9];
    const float* b4  = (const float*)d_in[10];
    float* out = (float*)d_out;

    // Resolve __device__ symbol addresses for the parameterized kernels.
    float *q2T_p, *q3T_p, *rs2_p, *rs3_p, *cur2_p, *cur3_p;
    unsigned *m1_p, *m2_p, *m3_p;
    int *f1_p, *f2_p;
    cudaGetSymbolAddress((void**)&q2T_p, g_q2T);
    cudaGetSymbolAddress((void**)&q3T_p, g_q3T);
    cudaGetSymbolAddress((void**)&rs2_p, g_rs2);
    cudaGetSymbolAddress((void**)&rs3_p, g_rs3);
    cudaGetSymbolAddress((void**)&cur2_p, g_cur2);
    cudaGetSymbolAddress((void**)&cur3_p, g_cur3);
    cudaGetSymbolAddress((void**)&m1_p, g_m1);
    cudaGetSymbolAddress((void**)&m2_p, g_m2);
    cudaGetSymbolAddress((void**)&m3_p, g_m3);
    cudaGetSymbolAddress((void**)&f1_p, g_f1);
    cudaGetSymbolAddress((void**)&f2_p, g_f2);

    cudaFuncSetAttribute(cur1_k, cudaFuncAttributeMaxDynamicSharedMemorySize,
                         SW_BYTES);

    float* o_s1 = out;
    float* o_s2 = out + SPK_HID;
    float* o_s3 = out + 2 * SPK_HID;

    prep_quant<<<1024, 256>>>(W1, W2, W3, W4);
    cochlea_rs<<<BATCH, 256>>>(x, Wch, cb);
    cur1_k<<<dim3(BATCH, T_STEPS / CH2), 512, SW_BYTES>>>();
    rec1_k<<<(BATCH * N_HID) / 128, 128>>>(b1, o_s1);
    cor_hid_k<<<dim3(BATCH, T_STEPS / 4), 512>>>(m1_p, q2T_p, rs2_p, cur2_p, f1_p);
    rec_mid_k<<<(BATCH * N_HID) / 128, 128>>>(f1_p, cur2_p, rs2_p, b2, o_s2, m2_p);
    cor_hid_k<<<dim3(BATCH, T_STEPS / 4), 512>>>(m2_p, q3T_p, rs3_p, cur3_p, f2_p);
    rec_mid_k<<<(BATCH * N_HID) / 128, 128>>>(f2_p, cur3_p, rs3_p, b3, o_s3, m3_p);
    cor_out_k<<<dim3(BATCH, T_STEPS / 4), 64>>>();
    rec_out_k<<<(BATCH * N_OUT + 127) / 128, 128>>>(b4, out);
}